// round 1
// baseline (speedup 1.0000x reference)
#include <cuda_runtime.h>
#include <math.h>

// Problem constants
#define BN   8
#define TN   16
#define CINC 3
#define HD   64
#define HH   64
#define WWN  64
#define HW   4096

// Tiling
#define TW    32          // spatial tile width
#define TH    8           // spatial tile height
#define COT   16          // output channels per block
#define CHUNK 4           // h/c channels per smem stage
#define RS    35          // patch row stride (odd-ish -> conflict-free strided reads)
#define PATCH ((TH + 2) * RS)   // 10*35 = 350 floats per channel patch

// c-state ping-pong buffers (no allocs allowed -> device globals). 2 * 8MB.
__device__ float g_c[2][BN * HD * HW];

// ---- packed fp32x2 helpers (Blackwell FFMA2: 2 MACs per issue) ----
__device__ __forceinline__ void ffma2(unsigned long long &d,
                                      unsigned long long a,
                                      unsigned long long b) {
    asm("fma.rn.f32x2 %0, %1, %2, %0;" : "+l"(d) : "l"(a), "l"(b));
}
__device__ __forceinline__ unsigned long long pack2(float x, float y) {
    unsigned long long r;
    asm("mov.b64 %0, {%1, %2};" : "=l"(r) : "f"(x), "f"(y));
    return r;
}
__device__ __forceinline__ float2 unpack2(unsigned long long v) {
    float2 r;
    asm("mov.b64 {%0, %1}, %2;" : "=f"(r.x), "=f"(r.y) : "l"(v));
    return r;
}

__device__ __forceinline__ float sigmoidf_(float x) {
    return 1.0f / (1.0f + __expf(-x));
}

// One LSTM timestep: fused 4-conv + pointwise update.
// Grid: (16 spatial tiles, 4 co tiles, 8 batch). Block: (8,8,4) = 256 threads.
// Thread computes 4 output channels x 4 consecutive x-pixels.
template <bool FIRST, bool LAST>
__global__ void __launch_bounds__(256, 2)
lstm_step(const float *__restrict__ input, const float *__restrict__ timet,
          const float *__restrict__ Wi, const float *__restrict__ bi,
          const float *__restrict__ Wct, const float *__restrict__ bct,
          const float *__restrict__ Wo, const float *__restrict__ bo,
          const float *__restrict__ Wcs, const float *__restrict__ bcs,
          float *__restrict__ out, float *__restrict__ hlast,
          float *__restrict__ clast, int t) {
    __shared__ float sp[(CHUNK * 2) * PATCH];                  // input patches
    __shared__ unsigned long long wsm[4][CHUNK][COT][9];       // weights as (w,w)

    const int tx = threadIdx.x;   // 0..7  (x groups of 4 px)
    const int ty = threadIdx.y;   // 0..7  (rows)
    const int tz = threadIdx.z;   // 0..3  (co groups of 4)
    const int tid = tx + 8 * ty + 64 * tz;

    const int tile_x = (blockIdx.x & 1) * TW;
    const int tile_y = (blockIdx.x >> 1) * TH;
    const int co_base = blockIdx.y * COT;
    const int b = blockIdx.z;

    const float *xb  = input + ((size_t)(b * TN + t) * CINC) * HW;
    const float *tmb = timet + ((size_t)(b * TN + t)) * HW;
    float *outb = out + ((size_t)(b * TN + t) * HD) * HW;
    const float *hprev = FIRST ? nullptr
                               : out + ((size_t)(b * TN + t - 1) * HD) * HW;
    const float *cprev = &g_c[t & 1][(size_t)b * HD * HW];
    float *cnext = &g_c[(t & 1) ^ 1][(size_t)b * HD * HW];

    // Accumulators: [co(4)][px-pair(2)] packed fp32x2, per conv tensor.
    unsigned long long ai[4][2], aq[4][2], ao[4][2], acs[4][2];
#pragma unroll
    for (int j = 0; j < 4; j++) {
        int co = co_base + tz * 4 + j;
        float v;
        v = bi[co];  ai[j][0] = pack2(v, v);  ai[j][1] = pack2(v, v);
        v = bct[co]; aq[j][0] = pack2(v, v);  aq[j][1] = pack2(v, v);
        v = bo[co];  ao[j][0] = pack2(v, v);  ao[j][1] = pack2(v, v);
        v = bcs[co]; acs[j][0] = pack2(v, v); acs[j][1] = pack2(v, v);
    }

    auto load_patch = [&](int slot, const float *plane) {
        for (int idx = tid; idx < PATCH; idx += 256) {
            int r = idx / RS;
            int cc = idx - r * RS;
            int gy = tile_y - 1 + r;
            int gx = tile_x - 1 + cc;
            float v = 0.0f;
            if (cc < TW + 2 && (unsigned)gy < HH && (unsigned)gx < WWN)
                v = plane[gy * WWN + gx];
            sp[slot * PATCH + idx] = v;
        }
    };

    // ================= stage 0: x channels (3) + time channel =================
    load_patch(0, xb + 0 * HW);
    load_patch(1, xb + 1 * HW);
    load_patch(2, xb + 2 * HW);
    load_patch(3, tmb);
    {
        const int NX = 3 * 3 * COT * 9;  // 3 tensors x 3 ci x 16 co x 9
        for (int idx = tid; idx < NX + COT * 9; idx += 256) {
            if (idx < NX) {
                int k = idx % 9;
                int r = idx / 9;
                int co = r % COT; r /= COT;
                int ci = r % 3;
                int tns = r / 3;
                int cog = co_base + co;
                float w;
                if (tns == 0)      w = Wi[((size_t)cog * 67 + ci) * 9 + k];
                else if (tns == 1) w = Wct[((size_t)cog * 67 + ci) * 9 + k];
                else               w = Wo[((size_t)cog * 68 + ci) * 9 + k];
                wsm[tns][ci][co][k] = pack2(w, w);
            } else {
                int r = idx - NX;
                int k = r % 9;
                int co = r / 9;
                float w = Wo[((size_t)(co_base + co) * 68 + 67) * 9 + k];
                wsm[3][0][co][k] = pack2(w, w);
            }
        }
    }
    __syncthreads();

#pragma unroll
    for (int ci = 0; ci < 3; ci++) {
        const float *pb = sp + ci * PATCH;
#pragma unroll
        for (int ky = 0; ky < 3; ky++) {
            int rb = (ty + ky) * RS + tx * 4;
            float v[6];
#pragma unroll
            for (int q = 0; q < 6; q++) v[q] = pb[rb + q];
            unsigned long long p[5];
#pragma unroll
            for (int q = 0; q < 5; q++) p[q] = pack2(v[q], v[q + 1]);
#pragma unroll
            for (int kx = 0; kx < 3; kx++) {
#pragma unroll
                for (int j = 0; j < 4; j++) {
                    int cw = tz * 4 + j, kk = ky * 3 + kx;
                    unsigned long long w;
                    w = wsm[0][ci][cw][kk]; ffma2(ai[j][0], p[kx], w); ffma2(ai[j][1], p[kx + 2], w);
                    w = wsm[1][ci][cw][kk]; ffma2(aq[j][0], p[kx], w); ffma2(aq[j][1], p[kx + 2], w);
                    w = wsm[2][ci][cw][kk]; ffma2(ao[j][0], p[kx], w); ffma2(ao[j][1], p[kx + 2], w);
                }
            }
        }
    }
    {   // time channel -> o-gate conv only
        const float *pb = sp + 3 * PATCH;
#pragma unroll
        for (int ky = 0; ky < 3; ky++) {
            int rb = (ty + ky) * RS + tx * 4;
            float v[6];
#pragma unroll
            for (int q = 0; q < 6; q++) v[q] = pb[rb + q];
            unsigned long long p[5];
#pragma unroll
            for (int q = 0; q < 5; q++) p[q] = pack2(v[q], v[q + 1]);
#pragma unroll
            for (int kx = 0; kx < 3; kx++) {
#pragma unroll
                for (int j = 0; j < 4; j++) {
                    unsigned long long w = wsm[3][0][tz * 4 + j][ky * 3 + kx];
                    ffma2(ao[j][0], p[kx], w);
                    ffma2(ao[j][1], p[kx + 2], w);
                }
            }
        }
    }

    // ================= stages over h/c channels (skip at t==0) =================
    if (!FIRST) {
        for (int j0 = 0; j0 < HD; j0 += CHUNK) {
            __syncthreads();
#pragma unroll
            for (int cc = 0; cc < CHUNK; cc++) {
                load_patch(cc, hprev + (size_t)(j0 + cc) * HW);
                load_patch(CHUNK + cc, cprev + (size_t)(j0 + cc) * HW);
            }
            for (int idx = tid; idx < 4 * CHUNK * COT * 9; idx += 256) {
                int k = idx % 9;
                int r = idx / 9;
                int co = r % COT; r /= COT;
                int cc = r % CHUNK;
                int tns = r / CHUNK;
                int cog = co_base + co;
                int j = j0 + cc;
                float w;
                if (tns == 0)      w = Wi[((size_t)cog * 67 + 3 + j) * 9 + k];
                else if (tns == 1) w = Wct[((size_t)cog * 67 + 3 + j) * 9 + k];
                else if (tns == 2) w = Wo[((size_t)cog * 68 + 3 + j) * 9 + k];
                else               w = Wcs[((size_t)cog * 64 + j) * 9 + k];
                wsm[tns][cc][co][k] = pack2(w, w);
            }
            __syncthreads();

#pragma unroll
            for (int cc = 0; cc < CHUNK; cc++) {
                const float *ph = sp + cc * PATCH;
                const float *pc = sp + (CHUNK + cc) * PATCH;
#pragma unroll
                for (int ky = 0; ky < 3; ky++) {
                    int rb = (ty + ky) * RS + tx * 4;
                    {   // h contribution -> i, ct, o convs
                        float v[6];
#pragma unroll
                        for (int q = 0; q < 6; q++) v[q] = ph[rb + q];
                        unsigned long long p[5];
#pragma unroll
                        for (int q = 0; q < 5; q++) p[q] = pack2(v[q], v[q + 1]);
#pragma unroll
                        for (int kx = 0; kx < 3; kx++) {
#pragma unroll
                            for (int j = 0; j < 4; j++) {
                                int cw = tz * 4 + j, kk = ky * 3 + kx;
                                unsigned long long w;
                                w = wsm[0][cc][cw][kk]; ffma2(ai[j][0], p[kx], w); ffma2(ai[j][1], p[kx + 2], w);
                                w = wsm[1][cc][cw][kk]; ffma2(aq[j][0], p[kx], w); ffma2(aq[j][1], p[kx + 2], w);
                                w = wsm[2][cc][cw][kk]; ffma2(ao[j][0], p[kx], w); ffma2(ao[j][1], p[kx + 2], w);
                            }
                        }
                    }
                    {   // c contribution -> cs conv
                        float v[6];
#pragma unroll
                        for (int q = 0; q < 6; q++) v[q] = pc[rb + q];
                        unsigned long long p[5];
#pragma unroll
                        for (int q = 0; q < 5; q++) p[q] = pack2(v[q], v[q + 1]);
#pragma unroll
                        for (int kx = 0; kx < 3; kx++) {
#pragma unroll
                            for (int j = 0; j < 4; j++) {
                                unsigned long long w = wsm[3][cc][tz * 4 + j][ky * 3 + kx];
                                ffma2(acs[j][0], p[kx], w);
                                ffma2(acs[j][1], p[kx + 2], w);
                            }
                        }
                    }
                }
            }
        }
    }

    // ================= epilogue: pointwise LSTM update =================
    const int y = tile_y + ty;
    const int x0 = tile_x + tx * 4;
    float tmv[4];
#pragma unroll
    for (int px = 0; px < 4; px++) tmv[px] = tanhf(tmb[y * WWN + x0 + px]);

#pragma unroll
    for (int j = 0; j < 4; j++) {
        int co = co_base + tz * 4 + j;
        size_t pbase = (size_t)co * HW + (size_t)y * WWN + x0;
        float2 i01 = unpack2(ai[j][0]),  i23 = unpack2(ai[j][1]);
        float2 q01 = unpack2(aq[j][0]),  q23 = unpack2(aq[j][1]);
        float2 o01 = unpack2(ao[j][0]),  o23 = unpack2(ao[j][1]);
        float2 s01 = unpack2(acs[j][0]), s23 = unpack2(acs[j][1]);
        float fi[4] = {i01.x, i01.y, i23.x, i23.y};
        float fq[4] = {q01.x, q01.y, q23.x, q23.y};
        float fo[4] = {o01.x, o01.y, o23.x, o23.y};
        float fs[4] = {s01.x, s01.y, s23.x, s23.y};
#pragma unroll
        for (int px = 0; px < 4; px++) {
            float ig = sigmoidf_(fi[px]);               // f gate == i gate (ref bug preserved)
            float cS = fs[px];
            float cp = FIRST ? 0.0f : cprev[pbase + px];
            float cstar = cp - cS * (1.0f + tmv[px]);   // (c - cS) - cS*tanh(tm)
            float ctl = tanhf(fq[px]);
            float cn = ig * (cstar + ctl);
            float og = sigmoidf_(fo[px]);
            float hn = og * tanhf(cn);
            outb[pbase + px] = hn;
            cnext[pbase + px] = cn;
            if (LAST && hlast != nullptr) {
                size_t lb = ((size_t)b * HD + co) * HW + (size_t)y * WWN + x0 + px;
                hlast[lb] = hn;
                clast[lb] = cn;
            }
        }
    }
}

extern "C" void kernel_launch(void *const *d_in, const int *in_sizes, int n_in,
                              void *d_out, int out_size) {
    (void)in_sizes; (void)n_in;
    const float *input = (const float *)d_in[0];
    const float *timet = (const float *)d_in[1];
    const float *Wi  = (const float *)d_in[2];
    const float *bi  = (const float *)d_in[3];
    const float *Wct = (const float *)d_in[4];
    const float *bct = (const float *)d_in[5];
    const float *Wo  = (const float *)d_in[6];
    const float *bo  = (const float *)d_in[7];
    const float *Wcs = (const float *)d_in[8];
    const float *bcs = (const float *)d_in[9];
    float *out = (float *)d_out;

    const size_t layer_elems = (size_t)BN * TN * HD * HW;   // 33,554,432
    const size_t hc = (size_t)BN * HD * HW;                 // 2,097,152
    const bool tail = (size_t)out_size >= layer_elems + 2 * hc;
    float *hlast = tail ? out + layer_elems : nullptr;
    float *clast = tail ? out + layer_elems + hc : nullptr;

    dim3 grid(16, HD / COT, BN);
    dim3 block(8, 8, 4);
    for (int t = 0; t < TN; t++) {
        if (t == 0)
            lstm_step<true, false><<<grid, block>>>(input, timet, Wi, bi, Wct, bct,
                                                    Wo, bo, Wcs, bcs, out, nullptr,
                                                    nullptr, t);
        else if (t == TN - 1)
            lstm_step<false, true><<<grid, block>>>(input, timet, Wi, bi, Wct, bct,
                                                    Wo, bo, Wcs, bcs, out, hlast,
                                                    clast, t);
        else
            lstm_step<false, false><<<grid, block>>>(input, timet, Wi, bi, Wct, bct,
                                                     Wo, bo, Wcs, bcs, out, nullptr,
                                                     nullptr, t);
    }
}

// round 2
// speedup vs baseline: 1.1631x; 1.1631x over previous
#include <cuda_runtime.h>
#include <math.h>

#define BN   8
#define TN   16
#define CINC 3
#define HD   64
#define HH   64
#define WWN  64
#define HW   4096

#define TW    32
#define TH    8
#define COT   16
#define NCP   8
#define CHUNK 4
#define RS64  34
#define PATCH64 ((TH + 2) * RS64)

typedef unsigned long long u64;

__device__ float g_c[2][BN * HD * HW];

__device__ __forceinline__ void ffma2(u64 &d, u64 a, u64 b) {
    asm("fma.rn.f32x2 %0, %1, %2, %0;" : "+l"(d) : "l"(a), "l"(b));
}
__device__ __forceinline__ u64 pack2(float x, float y) {
    u64 r;
    asm("mov.b64 %0, {%1, %2};" : "=l"(r) : "f"(x), "f"(y));
    return r;
}
__device__ __forceinline__ float2 unpack2(u64 v) {
    float2 r;
    asm("mov.b64 {%0, %1}, %2;" : "=f"(r.x), "=f"(r.y) : "l"(v));
    return r;
}
__device__ __forceinline__ float sigmoidf_(float x) {
    return 1.0f / (1.0f + __expf(-x));
}

template <bool FIRST, bool LAST>
__global__ void __launch_bounds__(256, 2)
lstm_step(const float *__restrict__ input, const float *__restrict__ timet,
          const float *__restrict__ Wi, const float *__restrict__ bi,
          const float *__restrict__ Wct, const float *__restrict__ bct,
          const float *__restrict__ Wo, const float *__restrict__ bo,
          const float *__restrict__ Wcs, const float *__restrict__ bcs,
          float *__restrict__ out, float *__restrict__ hlast,
          float *__restrict__ clast, int t) {
    __shared__ u64 sp[(CHUNK * 2) * PATCH64];        // patches, (v,v) duplicated
    __shared__ u64 wsm[4][CHUNK][NCP][9];            // weights, (w_co, w_co+1)

    const int tx = threadIdx.x;   // 0..7
    const int ty = threadIdx.y;   // 0..7
    const int tz = threadIdx.z;   // 0..3
    const int tid = tx + 8 * ty + 64 * tz;

    const int tile_x = (blockIdx.x & 1) * TW;
    const int tile_y = (blockIdx.x >> 1) * TH;
    const int co_base = blockIdx.y * COT;
    const int b = blockIdx.z;

    const float *xb  = input + ((size_t)(b * TN + t) * CINC) * HW;
    const float *tmb = timet + ((size_t)(b * TN + t)) * HW;
    float *outb = out + ((size_t)(b * TN + t) * HD) * HW;
    const float *hprev = FIRST ? nullptr
                               : out + ((size_t)(b * TN + t - 1) * HD) * HW;
    const float *cprev = &g_c[t & 1][(size_t)b * HD * HW];
    float *cnext = &g_c[(t & 1) ^ 1][(size_t)b * HD * HW];

    // Accumulators: [tensor(4: i,ct,o,cs)][copair(2)][px(4)]
    u64 acc[4][2][4];
#pragma unroll
    for (int jp = 0; jp < 2; jp++) {
        int co0 = co_base + tz * 4 + jp * 2;
        u64 v;
        v = pack2(bi[co0], bi[co0 + 1]);
#pragma unroll
        for (int px = 0; px < 4; px++) acc[0][jp][px] = v;
        v = pack2(bct[co0], bct[co0 + 1]);
#pragma unroll
        for (int px = 0; px < 4; px++) acc[1][jp][px] = v;
        v = pack2(bo[co0], bo[co0 + 1]);
#pragma unroll
        for (int px = 0; px < 4; px++) acc[2][jp][px] = v;
        v = pack2(bcs[co0], bcs[co0 + 1]);
#pragma unroll
        for (int px = 0; px < 4; px++) acc[3][jp][px] = v;
    }

    auto load_patch = [&](int slot, const float *plane) {
        for (int idx = tid; idx < PATCH64; idx += 256) {
            int r = idx / RS64;
            int cc = idx - r * RS64;
            int gy = tile_y - 1 + r;
            int gx = tile_x - 1 + cc;
            float v = 0.0f;
            if ((unsigned)gy < HH && (unsigned)gx < WWN)
                v = plane[gy * WWN + gx];
            sp[slot * PATCH64 + idx] = pack2(v, v);
        }
    };

    // h/x channel -> tensors i, ct, o (weights wsm[0..2][cc])
    auto conv_patch3 = [&](const u64 *pb, int cc) {
#pragma unroll
        for (int ky = 0; ky < 3; ky++) {
            const int rb = (ty + ky) * RS64 + tx * 4;
            u64 pv[6];
#pragma unroll
            for (int q = 0; q < 6; q++) pv[q] = pb[rb + q];
#pragma unroll
            for (int kx = 0; kx < 3; kx++) {
#pragma unroll
                for (int tns = 0; tns < 3; tns++) {
#pragma unroll
                    for (int jp = 0; jp < 2; jp++) {
                        u64 w = wsm[tns][cc][tz * 2 + jp][ky * 3 + kx];
#pragma unroll
                        for (int px = 0; px < 4; px++)
                            ffma2(acc[tns][jp][px], pv[kx + px], w);
                    }
                }
            }
        }
    };
    // single-tensor conv: weights from wsm[wsel][cc], accumulate into acc[asel]
    auto conv_patch1 = [&](const u64 *pb, int cc, int wsel, int asel) {
#pragma unroll
        for (int ky = 0; ky < 3; ky++) {
            const int rb = (ty + ky) * RS64 + tx * 4;
            u64 pv[6];
#pragma unroll
            for (int q = 0; q < 6; q++) pv[q] = pb[rb + q];
#pragma unroll
            for (int kx = 0; kx < 3; kx++) {
#pragma unroll
                for (int jp = 0; jp < 2; jp++) {
                    u64 w = wsm[wsel][cc][tz * 2 + jp][ky * 3 + kx];
#pragma unroll
                    for (int px = 0; px < 4; px++)
                        ffma2(acc[asel][jp][px], pv[kx + px], w);
                }
            }
        }
    };

    // ================= stage 0: x channels (3) + time channel =================
    load_patch(0, xb + 0 * HW);
    load_patch(1, xb + 1 * HW);
    load_patch(2, xb + 2 * HW);
    load_patch(3, tmb);
    {
        const int NX = 3 * 3 * NCP * 9;
        for (int idx = tid; idx < NX + NCP * 9; idx += 256) {
            if (idx < NX) {
                int k = idx % 9;
                int r = idx / 9;
                int cp = r % NCP; r /= NCP;
                int ci = r % 3;
                int tns = r / 3;
                int co0 = co_base + cp * 2;
                float w0, w1;
                if (tns == 0) {
                    w0 = Wi[((size_t)co0 * 67 + ci) * 9 + k];
                    w1 = Wi[((size_t)(co0 + 1) * 67 + ci) * 9 + k];
                } else if (tns == 1) {
                    w0 = Wct[((size_t)co0 * 67 + ci) * 9 + k];
                    w1 = Wct[((size_t)(co0 + 1) * 67 + ci) * 9 + k];
                } else {
                    w0 = Wo[((size_t)co0 * 68 + ci) * 9 + k];
                    w1 = Wo[((size_t)(co0 + 1) * 68 + ci) * 9 + k];
                }
                wsm[tns][ci][cp][k] = pack2(w0, w1);
            } else {
                int r = idx - NX;
                int k = r % 9;
                int cp = r / 9;
                int co0 = co_base + cp * 2;
                wsm[3][0][cp][k] = pack2(Wo[((size_t)co0 * 68 + 67) * 9 + k],
                                         Wo[((size_t)(co0 + 1) * 68 + 67) * 9 + k]);
            }
        }
    }
    __syncthreads();

#pragma unroll
    for (int ci = 0; ci < 3; ci++)
        conv_patch3(sp + ci * PATCH64, ci);
    conv_patch1(sp + 3 * PATCH64, 0, /*wsel=*/3, /*asel=*/2);  // time -> o gate

    // ================= stages over h/c channels (skip at t==0) =================
    if (!FIRST) {
        for (int j0 = 0; j0 < HD; j0 += CHUNK) {
            __syncthreads();
#pragma unroll
            for (int cc = 0; cc < CHUNK; cc++) {
                load_patch(cc, hprev + (size_t)(j0 + cc) * HW);
                load_patch(CHUNK + cc, cprev + (size_t)(j0 + cc) * HW);
            }
            for (int idx = tid; idx < 4 * CHUNK * NCP * 9; idx += 256) {
                int k = idx % 9;
                int r = idx / 9;
                int cp = r % NCP; r /= NCP;
                int cc = r % CHUNK;
                int tns = r / CHUNK;
                int co0 = co_base + cp * 2;
                int j = j0 + cc;
                float w0, w1;
                if (tns == 0) {
                    w0 = Wi[((size_t)co0 * 67 + 3 + j) * 9 + k];
                    w1 = Wi[((size_t)(co0 + 1) * 67 + 3 + j) * 9 + k];
                } else if (tns == 1) {
                    w0 = Wct[((size_t)co0 * 67 + 3 + j) * 9 + k];
                    w1 = Wct[((size_t)(co0 + 1) * 67 + 3 + j) * 9 + k];
                } else if (tns == 2) {
                    w0 = Wo[((size_t)co0 * 68 + 3 + j) * 9 + k];
                    w1 = Wo[((size_t)(co0 + 1) * 68 + 3 + j) * 9 + k];
                } else {
                    w0 = Wcs[((size_t)co0 * 64 + j) * 9 + k];
                    w1 = Wcs[((size_t)(co0 + 1) * 64 + j) * 9 + k];
                }
                wsm[tns][cc][cp][k] = pack2(w0, w1);
            }
            __syncthreads();

#pragma unroll
            for (int cc = 0; cc < CHUNK; cc++) {
                conv_patch3(sp + cc * PATCH64, cc);                       // h -> i,ct,o
                conv_patch1(sp + (CHUNK + cc) * PATCH64, cc, 3, 3);       // c -> cs
            }
        }
    }

    // ================= epilogue =================
    const int y = tile_y + ty;
    const int x0 = tile_x + tx * 4;
    float tmv[4];
#pragma unroll
    for (int px = 0; px < 4; px++) tmv[px] = tanhf(tmb[y * WWN + x0 + px]);

#pragma unroll
    for (int jp = 0; jp < 2; jp++) {
        float fi[2][4], fq[2][4], fo[2][4], fs[2][4];
#pragma unroll
        for (int px = 0; px < 4; px++) {
            float2 u;
            u = unpack2(acc[0][jp][px]); fi[0][px] = u.x; fi[1][px] = u.y;
            u = unpack2(acc[1][jp][px]); fq[0][px] = u.x; fq[1][px] = u.y;
            u = unpack2(acc[2][jp][px]); fo[0][px] = u.x; fo[1][px] = u.y;
            u = unpack2(acc[3][jp][px]); fs[0][px] = u.x; fs[1][px] = u.y;
        }
#pragma unroll
        for (int half = 0; half < 2; half++) {
            int co = co_base + tz * 4 + jp * 2 + half;
            size_t pbase = (size_t)co * HW + (size_t)y * WWN + x0;
#pragma unroll
            for (int px = 0; px < 4; px++) {
                float ig = sigmoidf_(fi[half][px]);       // f gate == i gate (ref bug)
                float cS = fs[half][px];
                float cp = FIRST ? 0.0f : cprev[pbase + px];
                float cstar = cp - cS * (1.0f + tmv[px]);
                float ctl = tanhf(fq[half][px]);
                float cn = ig * (cstar + ctl);
                float og = sigmoidf_(fo[half][px]);
                float hn = og * tanhf(cn);
                outb[pbase + px] = hn;
                cnext[pbase + px] = cn;
                if (LAST && hlast != nullptr) {
                    size_t lb = ((size_t)b * HD + co) * HW + (size_t)y * WWN + x0 + px;
                    hlast[lb] = hn;
                    clast[lb] = cn;
                }
            }
        }
    }
}

extern "C" void kernel_launch(void *const *d_in, const int *in_sizes, int n_in,
                              void *d_out, int out_size) {
    (void)in_sizes; (void)n_in;
    const float *input = (const float *)d_in[0];
    const float *timet = (const float *)d_in[1];
    const float *Wi  = (const float *)d_in[2];
    const float *bi  = (const float *)d_in[3];
    const float *Wct = (const float *)d_in[4];
    const float *bct = (const float *)d_in[5];
    const float *Wo  = (const float *)d_in[6];
    const float *bo  = (const float *)d_in[7];
    const float *Wcs = (const float *)d_in[8];
    const float *bcs = (const float *)d_in[9];
    float *out = (float *)d_out;

    const size_t layer_elems = (size_t)BN * TN * HD * HW;
    const size_t hc = (size_t)BN * HD * HW;
    const bool tail = (size_t)out_size >= layer_elems + 2 * hc;
    float *hlast = tail ? out + layer_elems : nullptr;
    float *clast = tail ? out + layer_elems + hc : nullptr;

    dim3 grid(16, HD / COT, BN);
    dim3 block(8, 8, 4);
    for (int t = 0; t < TN; t++) {
        if (t == 0)
            lstm_step<true, false><<<grid, block>>>(input, timet, Wi, bi, Wct, bct,
                                                    Wo, bo, Wcs, bcs, out, nullptr,
                                                    nullptr, t);
        else if (t == TN - 1)
            lstm_step<false, true><<<grid, block>>>(input, timet, Wi, bi, Wct, bct,
                                                    Wo, bo, Wcs, bcs, out, hlast,
                                                    clast, t);
        else
            lstm_step<false, false><<<grid, block>>>(input, timet, Wi, bi, Wct, bct,
                                                     Wo, bo, Wcs, bcs, out, nullptr,
                                                     nullptr, t);
    }
}

// round 3
// speedup vs baseline: 1.6342x; 1.4050x over previous
#include <cuda_runtime.h>
#include <math.h>
#include <stdint.h>

#define BN   8
#define TN   16
#define CINC 3
#define HD   64
#define HH   64
#define WWN  64
#define HW   4096

#define TW    32
#define TH    8
#define COT   16          // co per block = 8 copairs
#define CHUNK 4
#define RS32  35          // odd stride -> conflict-free LDS.32
#define PATCH32 (10 * RS32)            // 350 floats per channel patch
#define PBUF   (8 * PATCH32)           // 2800 floats per chunk buffer
#define WBUF   (4 * CHUNK * 8 * 9)     // 1152 u64 weights per chunk buffer

typedef unsigned long long u64;

__device__ float g_c[2][BN * HD * HW];

__device__ __forceinline__ void ffma2(u64 &d, u64 a, u64 b) {
    asm("fma.rn.f32x2 %0, %1, %2, %0;" : "+l"(d) : "l"(a), "l"(b));
}
__device__ __forceinline__ u64 pack2(float x, float y) {
    u64 r;
    asm("mov.b64 %0, {%1, %2};" : "=l"(r) : "f"(x), "f"(y));
    return r;
}
__device__ __forceinline__ u64 dup2(float x) {
    u64 r;
    asm("mov.b64 %0, {%1, %1};" : "=l"(r) : "f"(x));
    return r;
}
__device__ __forceinline__ float2 unpack2(u64 v) {
    float2 r;
    asm("mov.b64 {%0, %1}, %2;" : "=f"(r.x), "=f"(r.y) : "l"(v));
    return r;
}
__device__ __forceinline__ float sigmoidf_(float x) {
    return 1.0f / (1.0f + __expf(-x));
}
__device__ __forceinline__ void cp_async4(uint32_t dst, const void *src, uint32_t sz) {
    asm volatile("cp.async.ca.shared.global [%0], [%1], 4, %2;"
                 :: "r"(dst), "l"(src), "r"(sz));
}
__device__ __forceinline__ void cp_commit() {
    asm volatile("cp.async.commit_group;" ::: "memory");
}
__device__ __forceinline__ void cp_wait0() {
    asm volatile("cp.async.wait_group 0;" ::: "memory");
}

// Convolve one channel patch into NT tensors starting at weight-tensor T0,
// accumulating into acc[A0 .. A0+NT). px=8 pixels, one copair (tz) per thread.
template <int T0, int NT, int A0>
__device__ __forceinline__ void conv_ch(const float *__restrict__ pb,
                                        const u64 *__restrict__ wflat, int cc,
                                        int ty, int tx, int tz, u64 acc[4][8]) {
#pragma unroll
    for (int ky = 0; ky < 3; ky++) {
        const float *row = pb + (ty + ky) * RS32 + tx * 8;
        u64 pv[10];
#pragma unroll
        for (int q = 0; q < 10; q++) pv[q] = dup2(row[q]);
#pragma unroll
        for (int kx = 0; kx < 3; kx++) {
#pragma unroll
            for (int it = 0; it < NT; it++) {
                const int tns = T0 + it;
                u64 w = wflat[(((tns * CHUNK + cc) * 8 + tz) * 9) + ky * 3 + kx];
#pragma unroll
                for (int px = 0; px < 8; px++)
                    ffma2(acc[A0 + it][px], pv[kx + px], w);
            }
        }
    }
}

template <bool FIRST, bool LAST>
__global__ void __launch_bounds__(256, 2)
lstm_step(const float *__restrict__ input, const float *__restrict__ timet,
          const float *__restrict__ Wi, const float *__restrict__ bi,
          const float *__restrict__ Wct, const float *__restrict__ bct,
          const float *__restrict__ Wo, const float *__restrict__ bo,
          const float *__restrict__ Wcs, const float *__restrict__ bcs,
          float *__restrict__ out, float *__restrict__ hlast,
          float *__restrict__ clast, int t) {
    __shared__ float spf[2 * PBUF];     // 22.4 KB patches (plain fp32)
    __shared__ u64 wsmf[2 * WBUF];      // 18.4 KB weights (co-pair packed)

    const int tx = threadIdx.x;   // 0..3  (8-px groups)
    const int ty = threadIdx.y;   // 0..7  (rows)
    const int tz = threadIdx.z;   // 0..7  (copair)
    const int tid = tx + 4 * ty + 32 * tz;

    const int tile_x = (blockIdx.x & 1) * TW;
    const int tile_y = (blockIdx.x >> 1) * TH;
    const int co_base = blockIdx.y * COT;
    const int b = blockIdx.z;

    const float *xb  = input + ((size_t)(b * TN + t) * CINC) * HW;
    const float *tmb = timet + ((size_t)(b * TN + t)) * HW;
    float *outb = out + ((size_t)(b * TN + t) * HD) * HW;
    const float *hprev = FIRST ? nullptr
                               : out + ((size_t)(b * TN + t - 1) * HD) * HW;
    const float *cprev = &g_c[t & 1][(size_t)b * HD * HW];
    float *cnext = &g_c[(t & 1) ^ 1][(size_t)b * HD * HW];

    const uint32_t sp_sm = (uint32_t)__cvta_generic_to_shared(spf);

    // acc[tensor: i,ct,o,cs][px]
    u64 acc[4][8];
    {
        const int co0 = co_base + tz * 2;
        u64 v;
        v = pack2(bi[co0],  bi[co0 + 1]);
#pragma unroll
        for (int px = 0; px < 8; px++) acc[0][px] = v;
        v = pack2(bct[co0], bct[co0 + 1]);
#pragma unroll
        for (int px = 0; px < 8; px++) acc[1][px] = v;
        v = pack2(bo[co0],  bo[co0 + 1]);
#pragma unroll
        for (int px = 0; px < 8; px++) acc[2][px] = v;
        v = pack2(bcs[co0], bcs[co0 + 1]);
#pragma unroll
        for (int px = 0; px < 8; px++) acc[3][px] = v;
    }

    // ---- async patch loader: 8 channel patches of chunk j0 into buffer buf ----
    auto load_patches_async = [&](int buf, int j0) {
        const uint32_t dstb = sp_sm + (uint32_t)buf * PBUF * 4;
#pragma unroll
        for (int k = 0; k < 11; k++) {
            int e = tid + k * 256;
            if (e < PBUF) {
                int slot = e / PATCH32, pos = e % PATCH32;
                int r = pos / RS32, c = pos % RS32;
                int gy = tile_y - 1 + r, gx = tile_x - 1 + c;
                bool inb = (c < TW + 2) && ((unsigned)gy < HH) && ((unsigned)gx < WWN);
                const float *pl = (slot < 4)
                                      ? hprev + (size_t)(j0 + slot) * HW
                                      : cprev + (size_t)(j0 + slot - 4) * HW;
                const float *src = pl + (inb ? (gy * WWN + gx) : 0);
                cp_async4(dstb + (uint32_t)e * 4, src, inb ? 4u : 0u);
            }
        }
    };

    // ---- weight stage registers (next chunk) ----
    float wv0[5], wv1[5];
    auto load_wchunk_regs = [&](int j0) {
#pragma unroll
        for (int k = 0; k < 5; k++) {
            int e = tid + k * 256;
            if (e < WBUF) {
                int kk = e % 9, r = e / 9;
                int cp = r % 8, r2 = r / 8;
                int cc = r2 % CHUNK, tns = r2 / CHUNK;
                int co0 = co_base + cp * 2;
                int j = j0 + cc;
                if (tns == 0) {
                    wv0[k] = Wi[((size_t)co0 * 67 + 3 + j) * 9 + kk];
                    wv1[k] = Wi[((size_t)(co0 + 1) * 67 + 3 + j) * 9 + kk];
                } else if (tns == 1) {
                    wv0[k] = Wct[((size_t)co0 * 67 + 3 + j) * 9 + kk];
                    wv1[k] = Wct[((size_t)(co0 + 1) * 67 + 3 + j) * 9 + kk];
                } else if (tns == 2) {
                    wv0[k] = Wo[((size_t)co0 * 68 + 3 + j) * 9 + kk];
                    wv1[k] = Wo[((size_t)(co0 + 1) * 68 + 3 + j) * 9 + kk];
                } else {
                    wv0[k] = Wcs[((size_t)co0 * 64 + j) * 9 + kk];
                    wv1[k] = Wcs[((size_t)(co0 + 1) * 64 + j) * 9 + kk];
                }
            }
        }
    };
    auto store_wchunk = [&](int buf) {
#pragma unroll
        for (int k = 0; k < 5; k++) {
            int e = tid + k * 256;
            if (e < WBUF) wsmf[buf * WBUF + e] = pack2(wv0[k], wv1[k]);
        }
    };

    // ================= stage 0: x(3) + time patches into buffer 1 =================
    {
        const uint32_t dstb = sp_sm + (uint32_t)PBUF * 4;  // buf 1
#pragma unroll
        for (int k = 0; k < 6; k++) {
            int e = tid + k * 256;
            if (e < 4 * PATCH32) {
                int slot = e / PATCH32, pos = e % PATCH32;
                int r = pos / RS32, c = pos % RS32;
                int gy = tile_y - 1 + r, gx = tile_x - 1 + c;
                bool inb = (c < TW + 2) && ((unsigned)gy < HH) && ((unsigned)gx < WWN);
                const float *pl = (slot < 3) ? xb + (size_t)slot * HW : tmb;
                const float *src = pl + (inb ? (gy * WWN + gx) : 0);
                cp_async4(dstb + (uint32_t)e * 4, src, inb ? 4u : 0u);
            }
        }
        cp_commit();
        // stage-0 weights (direct): 3 tensors x 3 ci + time -> wsm buf 1
        for (int e = tid; e < 720; e += 256) {
            if (e < 648) {
                int kk = e % 9, r = e / 9;
                int cp = r % 8, r2 = r / 8;
                int ci = r2 % 3, tns = r2 / 3;
                int co0 = co_base + cp * 2;
                float w0, w1;
                if (tns == 0) {
                    w0 = Wi[((size_t)co0 * 67 + ci) * 9 + kk];
                    w1 = Wi[((size_t)(co0 + 1) * 67 + ci) * 9 + kk];
                } else if (tns == 1) {
                    w0 = Wct[((size_t)co0 * 67 + ci) * 9 + kk];
                    w1 = Wct[((size_t)(co0 + 1) * 67 + ci) * 9 + kk];
                } else {
                    w0 = Wo[((size_t)co0 * 68 + ci) * 9 + kk];
                    w1 = Wo[((size_t)(co0 + 1) * 68 + ci) * 9 + kk];
                }
                wsmf[WBUF + (((tns * CHUNK + ci) * 8 + cp) * 9) + kk] = pack2(w0, w1);
            } else {
                int e2 = e - 648;
                int kk = e2 % 9, cp = e2 / 9;
                int co0 = co_base + cp * 2;
                wsmf[WBUF + (((3 * CHUNK + 0) * 8 + cp) * 9) + kk] =
                    pack2(Wo[((size_t)co0 * 68 + 67) * 9 + kk],
                          Wo[((size_t)(co0 + 1) * 68 + 67) * 9 + kk]);
            }
        }
        cp_wait0();
        __syncthreads();
    }

    // prefetch chunk 0 while computing stage 0
    if (!FIRST) {
        load_patches_async(0, 0);
        cp_commit();
        load_wchunk_regs(0);
    }

    {   // stage-0 compute (reads buffer 1)
        const float *p1 = spf + PBUF;
        const u64 *w1 = wsmf + WBUF;
#pragma unroll 1
        for (int ci = 0; ci < 3; ci++)
            conv_ch<0, 3, 0>(p1 + ci * PATCH32, w1, ci, ty, tx, tz, acc);
        conv_ch<3, 1, 2>(p1 + 3 * PATCH32, w1, 0, ty, tx, tz, acc);  // time -> o
    }
    if (!FIRST) {
        cp_wait0();
        store_wchunk(0);
    }
    __syncthreads();

    // ================= pipelined chunk loop =================
    if (!FIRST) {
#pragma unroll 1
        for (int jc = 0; jc < HD / CHUNK; jc++) {
            const int buf = jc & 1;
            if (jc < HD / CHUNK - 1) {
                load_patches_async(buf ^ 1, (jc + 1) * CHUNK);
                cp_commit();
                load_wchunk_regs((jc + 1) * CHUNK);
            }
            const float *pb = spf + buf * PBUF;
            const u64 *wb = wsmf + buf * WBUF;
#pragma unroll 1
            for (int cc = 0; cc < CHUNK; cc++) {
                conv_ch<0, 3, 0>(pb + cc * PATCH32, wb, cc, ty, tx, tz, acc);       // h
                conv_ch<3, 1, 3>(pb + (CHUNK + cc) * PATCH32, wb, cc, ty, tx, tz, acc); // c
            }
            if (jc < HD / CHUNK - 1) {
                cp_wait0();
                store_wchunk(buf ^ 1);
            }
            __syncthreads();
        }
    }

    // ================= epilogue =================
    const int y = tile_y + ty;
    const int x0 = tile_x + tx * 8;
    float tmv[8];
#pragma unroll
    for (int px = 0; px < 8; px++) tmv[px] = tanhf(tmb[y * WWN + x0 + px]);

    float fi[2][8], fq[2][8], fo[2][8], fs[2][8];
#pragma unroll
    for (int px = 0; px < 8; px++) {
        float2 u;
        u = unpack2(acc[0][px]); fi[0][px] = u.x; fi[1][px] = u.y;
        u = unpack2(acc[1][px]); fq[0][px] = u.x; fq[1][px] = u.y;
        u = unpack2(acc[2][px]); fo[0][px] = u.x; fo[1][px] = u.y;
        u = unpack2(acc[3][px]); fs[0][px] = u.x; fs[1][px] = u.y;
    }
#pragma unroll
    for (int half = 0; half < 2; half++) {
        const int co = co_base + tz * 2 + half;
        const size_t pbase = (size_t)co * HW + (size_t)y * WWN + x0;
#pragma unroll
        for (int px = 0; px < 8; px++) {
            float ig = sigmoidf_(fi[half][px]);        // f gate == i gate (ref bug)
            float cS = fs[half][px];
            float cp = FIRST ? 0.0f : cprev[pbase + px];
            float cstar = cp - cS * (1.0f + tmv[px]);  // (c - cS) - cS*tanh(tm)
            float ctl = tanhf(fq[half][px]);
            float cn = ig * (cstar + ctl);
            float og = sigmoidf_(fo[half][px]);
            float hn = og * tanhf(cn);
            outb[pbase + px] = hn;
            cnext[pbase + px] = cn;
            if (LAST && hlast != nullptr) {
                size_t lb = ((size_t)b * HD + co) * HW + (size_t)y * WWN + x0 + px;
                hlast[lb] = hn;
                clast[lb] = cn;
            }
        }
    }
}

extern "C" void kernel_launch(void *const *d_in, const int *in_sizes, int n_in,
                              void *d_out, int out_size) {
    (void)in_sizes; (void)n_in;
    const float *input = (const float *)d_in[0];
    const float *timet = (const float *)d_in[1];
    const float *Wi  = (const float *)d_in[2];
    const float *bi  = (const float *)d_in[3];
    const float *Wct = (const float *)d_in[4];
    const float *bct = (const float *)d_in[5];
    const float *Wo  = (const float *)d_in[6];
    const float *bo  = (const float *)d_in[7];
    const float *Wcs = (const float *)d_in[8];
    const float *bcs = (const float *)d_in[9];
    float *out = (float *)d_out;

    const size_t layer_elems = (size_t)BN * TN * HD * HW;
    const size_t hc = (size_t)BN * HD * HW;
    const bool tail = (size_t)out_size >= layer_elems + 2 * hc;
    float *hlast = tail ? out + layer_elems : nullptr;
    float *clast = tail ? out + layer_elems + hc : nullptr;

    dim3 grid(16, HD / COT, BN);
    dim3 block(4, 8, 8);
    for (int t = 0; t < TN; t++) {
        if (t == 0)
            lstm_step<true, false><<<grid, block>>>(input, timet, Wi, bi, Wct, bct,
                                                    Wo, bo, Wcs, bcs, out, nullptr,
                                                    nullptr, t);
        else if (t == TN - 1)
            lstm_step<false, true><<<grid, block>>>(input, timet, Wi, bi, Wct, bct,
                                                    Wo, bo, Wcs, bcs, out, hlast,
                                                    clast, t);
        else
            lstm_step<false, false><<<grid, block>>>(input, timet, Wi, bi, Wct, bct,
                                                     Wo, bo, Wcs, bcs, out, nullptr,
                                                     nullptr, t);
    }
}

// round 4
// speedup vs baseline: 1.6817x; 1.0290x over previous
#include <cuda_runtime.h>
#include <math.h>
#include <stdint.h>

#define BN   8
#define TN   16
#define CINC 3
#define HD   64
#define HH   64
#define WWN  64
#define HW   4096

#define TW    32
#define TH    8
#define COT   16          // co per block = 8 copairs
#define CHUNK 4
#define RS32  36          // 16B-aligned rows for LDS.128
#define PATCH32 (10 * RS32)            // 360 floats per channel patch
#define PBUF   (8 * PATCH32)           // 2880 floats per chunk buffer
#define WBUF   (4 * CHUNK * 8 * 9)     // 1152 u64 weights per chunk buffer

typedef unsigned long long u64;

__device__ float g_c[2][BN * HD * HW];

__device__ __forceinline__ void ffma2(u64 &d, u64 a, u64 b) {
    asm("fma.rn.f32x2 %0, %1, %2, %0;" : "+l"(d) : "l"(a), "l"(b));
}
__device__ __forceinline__ u64 pack2(float x, float y) {
    u64 r;
    asm("mov.b64 %0, {%1, %2};" : "=l"(r) : "f"(x), "f"(y));
    return r;
}
__device__ __forceinline__ u64 dup2(float x) {
    u64 r;
    asm("mov.b64 %0, {%1, %1};" : "=l"(r) : "f"(x));
    return r;
}
__device__ __forceinline__ float2 unpack2(u64 v) {
    float2 r;
    asm("mov.b64 {%0, %1}, %2;" : "=f"(r.x), "=f"(r.y) : "l"(v));
    return r;
}
__device__ __forceinline__ float sigmoidf_(float x) {
    return 1.0f / (1.0f + __expf(-x));
}
__device__ __forceinline__ void cp_async4(uint32_t dst, const void *src, uint32_t sz) {
    asm volatile("cp.async.ca.shared.global [%0], [%1], 4, %2;"
                 :: "r"(dst), "l"(src), "r"(sz));
}
__device__ __forceinline__ void cp_commit() {
    asm volatile("cp.async.commit_group;" ::: "memory");
}
__device__ __forceinline__ void cp_wait0() {
    asm volatile("cp.async.wait_group 0;" ::: "memory");
}

// Load 10 pv values of one patch row as 3x float4 and duplicate into u64 lanes.
__device__ __forceinline__ void loadrow(const float *__restrict__ row, u64 pv[10]) {
    float4 a = *(const float4 *)(row);
    float4 b = *(const float4 *)(row + 4);
    float4 c = *(const float4 *)(row + 8);
    pv[0] = dup2(a.x); pv[1] = dup2(a.y); pv[2] = dup2(a.z); pv[3] = dup2(a.w);
    pv[4] = dup2(b.x); pv[5] = dup2(b.y); pv[6] = dup2(b.z); pv[7] = dup2(b.w);
    pv[8] = dup2(c.x); pv[9] = dup2(c.y);
}

template <bool FIRST, bool LAST>
__global__ void __launch_bounds__(256, 2)
lstm_step(const float *__restrict__ input, const float *__restrict__ timet,
          const float *__restrict__ Wi, const float *__restrict__ bi,
          const float *__restrict__ Wct, const float *__restrict__ bct,
          const float *__restrict__ Wo, const float *__restrict__ bo,
          const float *__restrict__ Wcs, const float *__restrict__ bcs,
          float *__restrict__ out, float *__restrict__ hlast,
          float *__restrict__ clast, int t) {
    __shared__ __align__(16) float spf[2 * PBUF];   // 23 KB patches
    __shared__ u64 wsmf[2 * WBUF];                  // 18.4 KB weights

    const int tx = threadIdx.x;   // 0..3  (8-px groups)
    const int ty = threadIdx.y;   // 0..7  (rows)
    const int tz = threadIdx.z;   // 0..7  (copair)
    const int tid = tx + 4 * ty + 32 * tz;

    const int tile_x = (blockIdx.x & 1) * TW;
    const int tile_y = (blockIdx.x >> 1) * TH;
    const int co_base = blockIdx.y * COT;
    const int b = blockIdx.z;

    const float *xb  = input + ((size_t)(b * TN + t) * CINC) * HW;
    const float *tmb = timet + ((size_t)(b * TN + t)) * HW;
    float *outb = out + ((size_t)(b * TN + t) * HD) * HW;
    const float *hprev = FIRST ? nullptr
                               : out + ((size_t)(b * TN + t - 1) * HD) * HW;
    const float *cprev = &g_c[t & 1][(size_t)b * HD * HW];
    float *cnext = &g_c[(t & 1) ^ 1][(size_t)b * HD * HW];

    const uint32_t sp_sm = (uint32_t)__cvta_generic_to_shared(spf);

    // acc[tensor: i,ct,o,cs][px]
    u64 acc[4][8];
    {
        const int co0 = co_base + tz * 2;
        u64 v;
        v = pack2(bi[co0],  bi[co0 + 1]);
#pragma unroll
        for (int px = 0; px < 8; px++) acc[0][px] = v;
        v = pack2(bct[co0], bct[co0 + 1]);
#pragma unroll
        for (int px = 0; px < 8; px++) acc[1][px] = v;
        v = pack2(bo[co0],  bo[co0 + 1]);
#pragma unroll
        for (int px = 0; px < 8; px++) acc[2][px] = v;
        v = pack2(bcs[co0], bcs[co0 + 1]);
#pragma unroll
        for (int px = 0; px < 8; px++) acc[3][px] = v;
    }

    // ---- async patch loader: 8 channel patches of chunk j0 into buffer buf ----
    auto load_patches_async = [&](int buf, int j0) {
        const uint32_t dstb = sp_sm + (uint32_t)buf * PBUF * 4;
#pragma unroll
        for (int k = 0; k < 12; k++) {
            int e = tid + k * 256;
            if (e < PBUF) {
                int slot = e / PATCH32, pos = e % PATCH32;
                int r = pos / RS32, c = pos % RS32;
                int gy = tile_y - 1 + r, gx = tile_x - 1 + c;
                bool inb = (c < TW + 2) && ((unsigned)gy < HH) && ((unsigned)gx < WWN);
                const float *pl = (slot < 4)
                                      ? hprev + (size_t)(j0 + slot) * HW
                                      : cprev + (size_t)(j0 + slot - 4) * HW;
                const float *src = pl + (inb ? (gy * WWN + gx) : 0);
                cp_async4(dstb + (uint32_t)e * 4, src, inb ? 4u : 0u);
            }
        }
    };

    // ---- weight stage registers (next chunk) ----
    float wv0[5], wv1[5];
    auto load_wchunk_regs = [&](int j0) {
#pragma unroll
        for (int k = 0; k < 5; k++) {
            int e = tid + k * 256;
            if (e < WBUF) {
                int kk = e % 9, r = e / 9;
                int cp = r % 8, r2 = r / 8;
                int cc = r2 % CHUNK, tns = r2 / CHUNK;
                int co0 = co_base + cp * 2;
                int j = j0 + cc;
                if (tns == 0) {
                    wv0[k] = Wi[((size_t)co0 * 67 + 3 + j) * 9 + kk];
                    wv1[k] = Wi[((size_t)(co0 + 1) * 67 + 3 + j) * 9 + kk];
                } else if (tns == 1) {
                    wv0[k] = Wct[((size_t)co0 * 67 + 3 + j) * 9 + kk];
                    wv1[k] = Wct[((size_t)(co0 + 1) * 67 + 3 + j) * 9 + kk];
                } else if (tns == 2) {
                    wv0[k] = Wo[((size_t)co0 * 68 + 3 + j) * 9 + kk];
                    wv1[k] = Wo[((size_t)(co0 + 1) * 68 + 3 + j) * 9 + kk];
                } else {
                    wv0[k] = Wcs[((size_t)co0 * 64 + j) * 9 + kk];
                    wv1[k] = Wcs[((size_t)(co0 + 1) * 64 + j) * 9 + kk];
                }
            }
        }
    };
    auto store_wchunk = [&](int buf) {
#pragma unroll
        for (int k = 0; k < 5; k++) {
            int e = tid + k * 256;
            if (e < WBUF) wsmf[buf * WBUF + e] = pack2(wv0[k], wv1[k]);
        }
    };

    // ================= stage 0: x(3) + time patches into buffer 1 =================
    {
        const uint32_t dstb = sp_sm + (uint32_t)PBUF * 4;  // buf 1
#pragma unroll
        for (int k = 0; k < 6; k++) {
            int e = tid + k * 256;
            if (e < 4 * PATCH32) {
                int slot = e / PATCH32, pos = e % PATCH32;
                int r = pos / RS32, c = pos % RS32;
                int gy = tile_y - 1 + r, gx = tile_x - 1 + c;
                bool inb = (c < TW + 2) && ((unsigned)gy < HH) && ((unsigned)gx < WWN);
                const float *pl = (slot < 3) ? xb + (size_t)slot * HW : tmb;
                const float *src = pl + (inb ? (gy * WWN + gx) : 0);
                cp_async4(dstb + (uint32_t)e * 4, src, inb ? 4u : 0u);
            }
        }
        cp_commit();
        for (int e = tid; e < 720; e += 256) {
            if (e < 648) {
                int kk = e % 9, r = e / 9;
                int cp = r % 8, r2 = r / 8;
                int ci = r2 % 3, tns = r2 / 3;
                int co0 = co_base + cp * 2;
                float w0, w1;
                if (tns == 0) {
                    w0 = Wi[((size_t)co0 * 67 + ci) * 9 + kk];
                    w1 = Wi[((size_t)(co0 + 1) * 67 + ci) * 9 + kk];
                } else if (tns == 1) {
                    w0 = Wct[((size_t)co0 * 67 + ci) * 9 + kk];
                    w1 = Wct[((size_t)(co0 + 1) * 67 + ci) * 9 + kk];
                } else {
                    w0 = Wo[((size_t)co0 * 68 + ci) * 9 + kk];
                    w1 = Wo[((size_t)(co0 + 1) * 68 + ci) * 9 + kk];
                }
                wsmf[WBUF + (((tns * CHUNK + ci) * 8 + cp) * 9) + kk] = pack2(w0, w1);
            } else {
                int e2 = e - 648;
                int kk = e2 % 9, cp = e2 / 9;
                int co0 = co_base + cp * 2;
                wsmf[WBUF + (((3 * CHUNK + 0) * 8 + cp) * 9) + kk] =
                    pack2(Wo[((size_t)co0 * 68 + 67) * 9 + kk],
                          Wo[((size_t)(co0 + 1) * 68 + 67) * 9 + kk]);
            }
        }
        cp_wait0();
        __syncthreads();
    }

    // prefetch chunk 0 while computing stage 0
    if (!FIRST) {
        load_patches_async(0, 0);
        cp_commit();
        load_wchunk_regs(0);
    }

    {   // stage-0 compute (reads buffer 1): x0,x1 fused pairwise; x2+time fused
        const float *p1 = spf + PBUF;
        const u64 *wb = wsmf + WBUF;
#pragma unroll
        for (int ky = 0; ky < 3; ky++) {
            u64 pva[10], pvb[10];
            loadrow(p1 + 0 * PATCH32 + (ty + ky) * RS32 + tx * 8, pva);
            loadrow(p1 + 1 * PATCH32 + (ty + ky) * RS32 + tx * 8, pvb);
#pragma unroll
            for (int kx = 0; kx < 3; kx++) {
#pragma unroll
                for (int tns = 0; tns < 3; tns++) {
                    u64 w0 = wb[(((tns * CHUNK + 0) * 8 + tz) * 9) + ky * 3 + kx];
                    u64 w1 = wb[(((tns * CHUNK + 1) * 8 + tz) * 9) + ky * 3 + kx];
#pragma unroll
                    for (int px = 0; px < 8; px++) {
                        ffma2(acc[tns][px], pva[kx + px], w0);
                        ffma2(acc[tns][px], pvb[kx + px], w1);
                    }
                }
            }
        }
#pragma unroll
        for (int ky = 0; ky < 3; ky++) {
            u64 pva[10], pvb[10];
            loadrow(p1 + 2 * PATCH32 + (ty + ky) * RS32 + tx * 8, pva);
            loadrow(p1 + 3 * PATCH32 + (ty + ky) * RS32 + tx * 8, pvb);
#pragma unroll
            for (int kx = 0; kx < 3; kx++) {
#pragma unroll
                for (int tns = 0; tns < 3; tns++) {
                    u64 w0 = wb[(((tns * CHUNK + 2) * 8 + tz) * 9) + ky * 3 + kx];
#pragma unroll
                    for (int px = 0; px < 8; px++)
                        ffma2(acc[tns][px], pva[kx + px], w0);
                }
                u64 wt = wb[(((3 * CHUNK + 0) * 8 + tz) * 9) + ky * 3 + kx];
#pragma unroll
                for (int px = 0; px < 8; px++)
                    ffma2(acc[2][px], pvb[kx + px], wt);   // time -> o gate
            }
        }
    }
    if (!FIRST) {
        cp_wait0();
        store_wchunk(0);
    }
    __syncthreads();

    // ================= pipelined chunk loop (fused h+c inner) =================
    if (!FIRST) {
#pragma unroll 1
        for (int jc = 0; jc < HD / CHUNK; jc++) {
            const int buf = jc & 1;
            if (jc < HD / CHUNK - 1) {
                load_patches_async(buf ^ 1, (jc + 1) * CHUNK);
                cp_commit();
                load_wchunk_regs((jc + 1) * CHUNK);
            }
            const float *pb = spf + buf * PBUF;
            const u64 *wb = wsmf + buf * WBUF;
#pragma unroll 2
            for (int cc = 0; cc < CHUNK; cc++) {
                const float *ph = pb + cc * PATCH32;
                const float *pc = pb + (CHUNK + cc) * PATCH32;
#pragma unroll
                for (int ky = 0; ky < 3; ky++) {
                    u64 pvh[10], pvc[10];
                    loadrow(ph + (ty + ky) * RS32 + tx * 8, pvh);
                    loadrow(pc + (ty + ky) * RS32 + tx * 8, pvc);
#pragma unroll
                    for (int kx = 0; kx < 3; kx++) {
#pragma unroll
                        for (int tns = 0; tns < 3; tns++) {
                            u64 w = wb[(((tns * CHUNK + cc) * 8 + tz) * 9) + ky * 3 + kx];
#pragma unroll
                            for (int px = 0; px < 8; px++)
                                ffma2(acc[tns][px], pvh[kx + px], w);
                        }
                        u64 wc = wb[(((3 * CHUNK + cc) * 8 + tz) * 9) + ky * 3 + kx];
#pragma unroll
                        for (int px = 0; px < 8; px++)
                            ffma2(acc[3][px], pvc[kx + px], wc);
                    }
                }
            }
            if (jc < HD / CHUNK - 1) {
                cp_wait0();
                store_wchunk(buf ^ 1);
            }
            __syncthreads();
        }
    }

    // ================= epilogue =================
    const int y = tile_y + ty;
    const int x0 = tile_x + tx * 8;
    float tmv[8];
#pragma unroll
    for (int px = 0; px < 8; px++) tmv[px] = tanhf(tmb[y * WWN + x0 + px]);

    float fi[2][8], fq[2][8], fo[2][8], fs[2][8];
#pragma unroll
    for (int px = 0; px < 8; px++) {
        float2 u;
        u = unpack2(acc[0][px]); fi[0][px] = u.x; fi[1][px] = u.y;
        u = unpack2(acc[1][px]); fq[0][px] = u.x; fq[1][px] = u.y;
        u = unpack2(acc[2][px]); fo[0][px] = u.x; fo[1][px] = u.y;
        u = unpack2(acc[3][px]); fs[0][px] = u.x; fs[1][px] = u.y;
    }
#pragma unroll
    for (int half = 0; half < 2; half++) {
        const int co = co_base + tz * 2 + half;
        const size_t pbase = (size_t)co * HW + (size_t)y * WWN + x0;
#pragma unroll
        for (int px = 0; px < 8; px++) {
            float ig = sigmoidf_(fi[half][px]);        // f gate == i gate (ref bug)
            float cS = fs[half][px];
            float cp = FIRST ? 0.0f : cprev[pbase + px];
            float cstar = cp - cS * (1.0f + tmv[px]);  // (c - cS) - cS*tanh(tm)
            float ctl = tanhf(fq[half][px]);
            float cn = ig * (cstar + ctl);
            float og = sigmoidf_(fo[half][px]);
            float hn = og * tanhf(cn);
            outb[pbase + px] = hn;
            cnext[pbase + px] = cn;
            if (LAST && hlast != nullptr) {
                size_t lb = ((size_t)b * HD + co) * HW + (size_t)y * WWN + x0 + px;
                hlast[lb] = hn;
                clast[lb] = cn;
            }
        }
    }
}

extern "C" void kernel_launch(void *const *d_in, const int *in_sizes, int n_in,
                              void *d_out, int out_size) {
    (void)in_sizes; (void)n_in;
    const float *input = (const float *)d_in[0];
    const float *timet = (const float *)d_in[1];
    const float *Wi  = (const float *)d_in[2];
    const float *bi  = (const float *)d_in[3];
    const float *Wct = (const float *)d_in[4];
    const float *bct = (const float *)d_in[5];
    const float *Wo  = (const float *)d_in[6];
    const float *bo  = (const float *)d_in[7];
    const float *Wcs = (const float *)d_in[8];
    const float *bcs = (const float *)d_in[9];
    float *out = (float *)d_out;

    const size_t layer_elems = (size_t)BN * TN * HD * HW;
    const size_t hc = (size_t)BN * HD * HW;
    const bool tail = (size_t)out_size >= layer_elems + 2 * hc;
    float *hlast = tail ? out + layer_elems : nullptr;
    float *clast = tail ? out + layer_elems + hc : nullptr;

    dim3 grid(16, HD / COT, BN);
    dim3 block(4, 8, 8);
    for (int t = 0; t < TN; t++) {
        if (t == 0)
            lstm_step<true, false><<<grid, block>>>(input, timet, Wi, bi, Wct, bct,
                                                    Wo, bo, Wcs, bcs, out, nullptr,
                                                    nullptr, t);
        else if (t == TN - 1)
            lstm_step<false, true><<<grid, block>>>(input, timet, Wi, bi, Wct, bct,
                                                    Wo, bo, Wcs, bcs, out, hlast,
                                                    clast, t);
        else
            lstm_step<false, false><<<grid, block>>>(input, timet, Wi, bi, Wct, bct,
                                                     Wo, bo, Wcs, bcs, out, nullptr,
                                                     nullptr, t);
    }
}